// round 13
// baseline (speedup 1.0000x reference)
#include <cuda_runtime.h>
#include <cuda_bf16.h>
#include <cstdint>
#include <cstddef>

#define DINL __device__ __forceinline__

// Problem dims
constexpr int BATCH = 8;
constexpr int CIN   = 256;
constexpr int COUT  = 256;
constexpr int HH = 64, WW = 64;
constexpr int HW = HH * WW;          // 4096
constexpr int KTOT = 9 * CIN;        // 2304
constexpr int KC   = 32;             // channels per K-chunk
constexpr int NCH  = KTOT / KC;      // 72 chunks
constexpr int NSTG = 2;              // pipeline stages (occ-2 config)

// Stage tile layout (bf16, 80B row stride -> conflict-free ldmatrix)
// A: 128 rows x 80B per plane; B: 128 rows x 80B per plane
constexpr int ST_AHI = 0;            // 10240
constexpr int ST_ALO = 10240;
constexpr int ST_BHI = 20480;
constexpr int ST_BLO = 30720;
constexpr int ST_SZ  = 40960;
constexpr int SMEM_BYTES = NSTG * ST_SZ;   // 81920 (epilogue needs 128*129*4=66048 <= this)

// Scratch (device globals; no runtime allocation allowed)
__device__ __align__(16) __nv_bfloat16 g_featHi[BATCH * HW * CIN];  // [b][pix][c]
__device__ __align__(16) __nv_bfloat16 g_featLo[BATCH * HW * CIN];
__device__ __align__(16) __nv_bfloat16 g_wHi[COUT * KTOT];          // [o][k]
__device__ __align__(16) __nv_bfloat16 g_wLo[COUT * KTOT];

// ---------------- prep kernels ----------------
__global__ void k_wsplit(const float* __restrict__ w) {
    int i = blockIdx.x * blockDim.x + threadIdx.x;
    if (i < COUT * KTOT / 4) {
        float4 v = reinterpret_cast<const float4*>(w)[i];
        __nv_bfloat16 h0 = __float2bfloat16(v.x), h1 = __float2bfloat16(v.y);
        __nv_bfloat16 h2 = __float2bfloat16(v.z), h3 = __float2bfloat16(v.w);
        __nv_bfloat162 hA = __nv_bfloat162(h0, h1), hB = __nv_bfloat162(h2, h3);
        __nv_bfloat162 lA = __nv_bfloat162(__float2bfloat16(v.x - __bfloat162float(h0)),
                                           __float2bfloat16(v.y - __bfloat162float(h1)));
        __nv_bfloat162 lB = __nv_bfloat162(__float2bfloat16(v.z - __bfloat162float(h2)),
                                           __float2bfloat16(v.w - __bfloat162float(h3)));
        reinterpret_cast<__nv_bfloat162*>(g_wHi)[i * 2]     = hA;
        reinterpret_cast<__nv_bfloat162*>(g_wHi)[i * 2 + 1] = hB;
        reinterpret_cast<__nv_bfloat162*>(g_wLo)[i * 2]     = lA;
        reinterpret_cast<__nv_bfloat162*>(g_wLo)[i * 2 + 1] = lB;
    }
}

// feat (B,C,H,W) fp32 -> planar hi/lo channels-last via 32x32 smem transpose
__global__ void k_split_feat(const float* __restrict__ feat) {
    __shared__ float tile[32][33];
    int b  = blockIdx.z;
    int c0 = blockIdx.y * 32;
    int p0 = blockIdx.x * 32;
    int tx = threadIdx.x, ty = threadIdx.y;   // (32, 8)
    const float* src = feat + (size_t)b * CIN * HW;
#pragma unroll
    for (int i = 0; i < 32; i += 8)
        tile[ty + i][tx] = src[(size_t)(c0 + ty + i) * HW + p0 + tx];
    __syncthreads();
#pragma unroll
    for (int i = 0; i < 32; i += 8) {
        float v = tile[tx][ty + i];
        __nv_bfloat16 hi = __float2bfloat16(v);
        __nv_bfloat16 lo = __float2bfloat16(v - __bfloat162float(hi));
        size_t o = ((size_t)b * HW + p0 + ty + i) * CIN + c0 + tx;
        g_featHi[o] = hi; g_featLo[o] = lo;
    }
}

// ---------------- asm helpers ----------------
DINL uint32_t smem_u32(const void* p) {
    uint32_t a;
    asm("{ .reg .u64 t; cvta.to.shared.u64 t, %1; cvt.u32.u64 %0, t; }" : "=r"(a) : "l"(p));
    return a;
}
DINL void cpasync16(uint32_t dst, const void* src) {
    asm volatile("cp.async.cg.shared.global [%0], [%1], 16;" :: "r"(dst), "l"(src));
}
DINL void cp_commit() { asm volatile("cp.async.commit_group;" ::: "memory"); }
DINL void cp_wait1()  { asm volatile("cp.async.wait_group 1;" ::: "memory"); }
DINL void ldsm4(uint32_t r[4], uint32_t addr) {
    asm volatile("ldmatrix.sync.aligned.m8n8.x4.shared.b16 {%0,%1,%2,%3}, [%4];"
                 : "=r"(r[0]), "=r"(r[1]), "=r"(r[2]), "=r"(r[3]) : "r"(addr));
}
DINL void mma16816(float c[4], const uint32_t a[4], uint32_t b0, uint32_t b1) {
    asm volatile("mma.sync.aligned.m16n8k16.row.col.f32.bf16.bf16.f32 "
                 "{%0,%1,%2,%3}, {%4,%5,%6,%7}, {%8,%9}, {%0,%1,%2,%3};"
                 : "+f"(c[0]), "+f"(c[1]), "+f"(c[2]), "+f"(c[3])
                 : "r"(a[0]), "r"(a[1]), "r"(a[2]), "r"(a[3]), "r"(b0), "r"(b1));
}

// ---------------- fused gather-GEMM (occupancy-2) ----------------
// Grid: 512 CTAs = 8 batches x 32 h-pairs x 2 N-halves. CTA tile M=128, N=128.
// 256 threads = 8 warps in 4m x 2n; warp tile 32x64 (same fragment math as before).
// 2 CTAs/SM: sibling CTA fills barrier/scoreboard bubbles.
__global__ void __launch_bounds__(256, 2)
k_gemm(const int* __restrict__ scx, const int* __restrict__ scy, float* __restrict__ out) {
    extern __shared__ __align__(128) char smem[];
    uint32_t sb = smem_u32(smem);
    int tid  = threadIdx.x;
    int lane = tid & 31, wid = tid >> 5;
    int wm = wid >> 1, wn = wid & 1;             // 4x2 warp grid
    int bx = blockIdx.x;
    int b  = bx >> 6;
    int rest = bx & 63;
    int h0 = (rest >> 1) * 2;
    int n0 = (rest & 1) * 128;                   // this CTA's N-half

    // copy mapping: each thread owns one A row-part and one B row-part (32B each)
    int arow  = tid >> 1, apart = tid & 1;       // A: 128 rows x 2 x 32B per plane
    int ah = h0 + (arow >> 6), aw = arow & 63;
    int apix0 = ah * WW + aw;
    int brow  = tid >> 1, bhalf = tid & 1;       // B: 128 rows x 2 x 32B per plane

    // Precompute the 9 gather-row element offsets (loop-invariant)
    uint32_t apixoff[9];
    {
        int asamp = apix0 * 8;
        apixoff[0] = (uint32_t)((b * HW + apix0) * CIN + apart * 16);
#pragma unroll
        for (int g = 1; g <= 8; ++g) {
            int si = asamp + g - 1;
            int pix = (__ldg(scy + si) - 1) * WW + (__ldg(scx + si) - 1);
            apixoff[g] = (uint32_t)((b * HW + pix) * CIN + apart * 16);
        }
    }

    // ldmatrix per-lane offsets (within a stage)
    uint32_t a_off = (uint32_t)((wm * 32 + (lane & 15)) * 80 + (lane >> 4) * 16);
    uint32_t b_off = (uint32_t)((wn * 64 + (lane & 7) + (lane >> 4) * 8) * 80
                                + ((lane >> 3) & 1) * 16);

    float acc[2][8][4];
#pragma unroll
    for (int mt = 0; mt < 2; ++mt)
#pragma unroll
        for (int nt = 0; nt < 8; ++nt)
#pragma unroll
            for (int j = 0; j < 4; ++j) acc[mt][nt][j] = 0.0f;

    // ---- issue cp.async copies for chunk s into stage s&1 ----
    auto issue = [&](int s) {
        uint32_t stg = sb + (uint32_t)((s & 1) * ST_SZ);
        int g  = s >> 3;
        int cb = (s & 7) * 32;
        size_t aoff = (size_t)apixoff[g] + cb;
        uint32_t sa = stg + (uint32_t)(arow * 80 + apart * 32);
        cpasync16(sa + ST_AHI,      g_featHi + aoff);
        cpasync16(sa + ST_AHI + 16, g_featHi + aoff + 8);
        cpasync16(sa + ST_ALO,      g_featLo + aoff);
        cpasync16(sa + ST_ALO + 16, g_featLo + aoff + 8);
        size_t boff = (size_t)(n0 + brow) * KTOT + s * 32 + bhalf * 16;
        uint32_t sbb = stg + (uint32_t)(brow * 80 + bhalf * 32);
        cpasync16(sbb + ST_BHI,      g_wHi + boff);
        cpasync16(sbb + ST_BHI + 16, g_wHi + boff + 8);
        cpasync16(sbb + ST_BLO,      g_wLo + boff);
        cpasync16(sbb + ST_BLO + 16, g_wLo + boff + 8);
    };

    // ---- compute one chunk from a stage (3-term bf16 fp32-emulation) ----
    auto mma_chunk = [&](uint32_t stg) {
        uint32_t Ahi = stg + ST_AHI + a_off, Alo = stg + ST_ALO + a_off;
        uint32_t Bhi = stg + ST_BHI + b_off, Blo = stg + ST_BLO + b_off;
        uint32_t ahr[2][4], alr[2][4], bb[4][4];
#pragma unroll
        for (int ks = 0; ks < 2; ++ks) {
            uint32_t ko = ks * 32;
            ldsm4(ahr[0], Ahi + ko);
            ldsm4(ahr[1], Ahi + ko + 16 * 80);
#pragma unroll
            for (int bt = 0; bt < 4; ++bt) ldsm4(bb[bt], Bhi + ko + bt * 16 * 80);
#pragma unroll
            for (int mt = 0; mt < 2; ++mt)
#pragma unroll
                for (int nt = 0; nt < 8; ++nt)
                    mma16816(acc[mt][nt], ahr[mt], bb[nt >> 1][(nt & 1) * 2], bb[nt >> 1][(nt & 1) * 2 + 1]);
            ldsm4(alr[0], Alo + ko);
            ldsm4(alr[1], Alo + ko + 16 * 80);
#pragma unroll
            for (int mt = 0; mt < 2; ++mt)
#pragma unroll
                for (int nt = 0; nt < 8; ++nt)
                    mma16816(acc[mt][nt], alr[mt], bb[nt >> 1][(nt & 1) * 2], bb[nt >> 1][(nt & 1) * 2 + 1]);
#pragma unroll
            for (int bt = 0; bt < 4; ++bt) ldsm4(bb[bt], Blo + ko + bt * 16 * 80);
#pragma unroll
            for (int mt = 0; mt < 2; ++mt)
#pragma unroll
                for (int nt = 0; nt < 8; ++nt)
                    mma16816(acc[mt][nt], ahr[mt], bb[nt >> 1][(nt & 1) * 2], bb[nt >> 1][(nt & 1) * 2 + 1]);
        }
    };

    // ---- 2-stage pipeline ----
    // Iter s: issue(s+1) -> stage (s+1)&1 (safe: mma(s-1) retired it at the
    // trailing barrier of iter s-1); wait retires group s; compute stage s&1.
    issue(0); cp_commit();
#pragma unroll 1
    for (int s = 0; s < NCH; ++s) {
        if (s + 1 < NCH) issue(s + 1);
        cp_commit();                      // uniform group count (empty at tail)
        cp_wait1();                       // group s complete
        __syncthreads();
        mma_chunk(sb + (uint32_t)((s & 1) * ST_SZ));
        __syncthreads();                  // stage s&1 retire: next iter may overwrite
    }

    // ---- epilogue: stage 128x128 fp32 (stride 129), then coalesced stores ----
    float* smf = reinterpret_cast<float*>(smem);
    {
        int r0 = wm * 32;
#pragma unroll
        for (int mt = 0; mt < 2; ++mt)
#pragma unroll
            for (int nt = 0; nt < 8; ++nt) {
                int r = r0 + mt * 16 + (lane >> 2);
                int c = wn * 64 + nt * 8 + (lane & 3) * 2;
                smf[r * 129 + c]           = acc[mt][nt][0];
                smf[r * 129 + c + 1]       = acc[mt][nt][1];
                smf[(r + 8) * 129 + c]     = acc[mt][nt][2];
                smf[(r + 8) * 129 + c + 1] = acc[mt][nt][3];
            }
    }
    __syncthreads();
    {
        int w   = tid & 63;
        int hh  = (tid >> 6) & 1;
        int ns0 = tid >> 7;                       // 2 n-streams of 64
        int m   = hh * 64 + w;
        size_t ob = (size_t)b * COUT * HW + (size_t)(h0 + hh) * WW + w;
#pragma unroll
        for (int i = 0; i < 64; ++i) {
            int n = ns0 * 64 + i;
            out[ob + (size_t)(n0 + n) * HW] = smf[m * 129 + n];
        }
    }
}

// ---------------- launch ----------------
extern "C" void kernel_launch(void* const* d_in, const int* in_sizes, int n_in,
                              void* d_out, int out_size) {
    const float* feat  = (const float*)d_in[0];
    const float* wconv = (const float*)d_in[1];
    const int*   scx   = (const int*)d_in[2];
    const int*   scy   = (const int*)d_in[3];
    float* out = (float*)d_out;

    k_split_feat<<<dim3(HW / 32, CIN / 32, BATCH), dim3(32, 8)>>>(feat);
    k_wsplit<<<(COUT * KTOT / 4 + 255) / 256, 256>>>(wconv);

    cudaFuncSetAttribute(k_gemm, cudaFuncAttributeMaxDynamicSharedMemorySize, SMEM_BYTES);
    k_gemm<<<BATCH * 32 * 2, 256, SMEM_BYTES>>>(scx, scy, out);
}

// round 15
// speedup vs baseline: 1.5084x; 1.5084x over previous
#include <cuda_runtime.h>
#include <cuda_fp16.h>
#include <cstdint>
#include <cstddef>

#define DINL __device__ __forceinline__

// Problem dims
constexpr int BATCH = 8;
constexpr int CIN   = 256;
constexpr int COUT  = 256;
constexpr int HH = 64, WW = 64;
constexpr int HW = HH * WW;          // 4096
constexpr int KTOT = 9 * CIN;        // 2304
constexpr int KC   = 32;             // channels per K-chunk
constexpr int NCH  = KTOT / KC;      // 72 chunks
constexpr int NSTG = 3;              // pipeline stages

// Stage tile layout (fp16, 80B row stride -> conflict-free ldmatrix)
// A: hi+lo planes, 128 rows x 80B each; B: single plane, 256 rows x 80B
constexpr int ST_AHI = 0;            // 10240
constexpr int ST_ALO = 10240;        // 10240
constexpr int ST_B   = 20480;        // 20480
constexpr int ST_SZ  = 40960;
constexpr int SMEM_BYTES = 131584;   // max(3*ST_SZ=122880, epilogue 128*257*4=131584)

// Scratch (device globals; no runtime allocation allowed)
__device__ __align__(16) __half g_featHi[BATCH * HW * CIN];  // [b][pix][c]
__device__ __align__(16) __half g_featLo[BATCH * HW * CIN];
__device__ __align__(16) __half g_wH[COUT * KTOT];           // [o][k] single fp16 plane

// ---------------- prep kernels ----------------
// weights: float4-vectorized fp16 round (single plane)
__global__ void k_wconv(const float* __restrict__ w) {
    int i = blockIdx.x * blockDim.x + threadIdx.x;
    if (i < COUT * KTOT / 4) {
        float4 v = reinterpret_cast<const float4*>(w)[i];
        __half2 a = __half2(__float2half(v.x), __float2half(v.y));
        __half2 b = __half2(__float2half(v.z), __float2half(v.w));
        reinterpret_cast<__half2*>(g_wH)[i * 2]     = a;
        reinterpret_cast<__half2*>(g_wH)[i * 2 + 1] = b;
    }
}

// feat (B,C,H,W) fp32 -> planar fp16 hi/lo channels-last via 32x32 smem transpose
__global__ void k_split_feat(const float* __restrict__ feat) {
    __shared__ float tile[32][33];
    int b  = blockIdx.z;
    int c0 = blockIdx.y * 32;
    int p0 = blockIdx.x * 32;
    int tx = threadIdx.x, ty = threadIdx.y;   // (32, 8)
    const float* src = feat + (size_t)b * CIN * HW;
#pragma unroll
    for (int i = 0; i < 32; i += 8)
        tile[ty + i][tx] = src[(size_t)(c0 + ty + i) * HW + p0 + tx];
    __syncthreads();
#pragma unroll
    for (int i = 0; i < 32; i += 8) {
        float v = tile[tx][ty + i];
        __half hi = __float2half(v);
        __half lo = __float2half(v - __half2float(hi));
        size_t o = ((size_t)b * HW + p0 + ty + i) * CIN + c0 + tx;
        g_featHi[o] = hi; g_featLo[o] = lo;
    }
}

// ---------------- asm helpers ----------------
DINL uint32_t smem_u32(const void* p) {
    uint32_t a;
    asm("{ .reg .u64 t; cvta.to.shared.u64 t, %1; cvt.u32.u64 %0, t; }" : "=r"(a) : "l"(p));
    return a;
}
DINL void cpasync16(uint32_t dst, const void* src) {
    asm volatile("cp.async.cg.shared.global [%0], [%1], 16;" :: "r"(dst), "l"(src));
}
DINL void cp_commit() { asm volatile("cp.async.commit_group;" ::: "memory"); }
DINL void cp_wait1()  { asm volatile("cp.async.wait_group 1;" ::: "memory"); }
DINL void ldsm4(uint32_t r[4], uint32_t addr) {
    asm volatile("ldmatrix.sync.aligned.m8n8.x4.shared.b16 {%0,%1,%2,%3}, [%4];"
                 : "=r"(r[0]), "=r"(r[1]), "=r"(r[2]), "=r"(r[3]) : "r"(addr));
}
DINL void mma16816(float c[4], const uint32_t a[4], uint32_t b0, uint32_t b1) {
    asm volatile("mma.sync.aligned.m16n8k16.row.col.f32.f16.f16.f32 "
                 "{%0,%1,%2,%3}, {%4,%5,%6,%7}, {%8,%9}, {%0,%1,%2,%3};"
                 : "+f"(c[0]), "+f"(c[1]), "+f"(c[2]), "+f"(c[3])
                 : "r"(a[0]), "r"(a[1]), "r"(a[2]), "r"(a[3]), "r"(b0), "r"(b1));
}

// ---------------- fused gather-GEMM ----------------
// Grid: 256 CTAs = 8 batches x 32 h-pairs. CTA tile M=128, N=256. Occupancy 1
// (proven best vs occ-2 in R12 bench). 512 threads = 16 warps in 4x4; warp tile
// 32x64. fp16 2-term emulation: D = (Ahi + Alo) * fp16(B); dropped A*Blo ~ 2^-12.
__global__ void __launch_bounds__(512, 1)
k_gemm(const int* __restrict__ scx, const int* __restrict__ scy, float* __restrict__ out) {
    extern __shared__ __align__(128) char smem[];
    uint32_t sb = smem_u32(smem);
    int tid  = threadIdx.x;
    int lane = tid & 31, wid = tid >> 5;
    int wm = wid >> 2, wn = wid & 3;             // 4x4 warp grid
    int b  = blockIdx.x >> 5;
    int h0 = (blockIdx.x & 31) * 2;

    // copy mapping: A 128 rows x 4 x 16B (x2 hi/lo); B 256 rows x 2 x 32B (1 plane)
    int arow  = tid >> 2, apart = tid & 3;
    int ah = h0 + (arow >> 6), aw = arow & 63;
    int apix0 = ah * WW + aw;
    int brow  = tid >> 1, bhalf = tid & 1;

    // Precompute the 9 gather-row element offsets (loop-invariant)
    uint32_t apixoff[9];
    {
        int asamp = apix0 * 8;
        apixoff[0] = (uint32_t)((b * HW + apix0) * CIN + apart * 8);
#pragma unroll
        for (int g = 1; g <= 8; ++g) {
            int si = asamp + g - 1;
            int pix = (__ldg(scy + si) - 1) * WW + (__ldg(scx + si) - 1);
            apixoff[g] = (uint32_t)((b * HW + pix) * CIN + apart * 8);
        }
    }

    // ldmatrix per-lane offsets (within a stage)
    uint32_t a_off = (uint32_t)((wm * 32 + (lane & 15)) * 80 + (lane >> 4) * 16);
    uint32_t b_off = (uint32_t)((wn * 64 + (lane & 7) + (lane >> 4) * 8) * 80
                                + ((lane >> 3) & 1) * 16);

    float acc[2][8][4];
#pragma unroll
    for (int mt = 0; mt < 2; ++mt)
#pragma unroll
        for (int nt = 0; nt < 8; ++nt)
#pragma unroll
            for (int j = 0; j < 4; ++j) acc[mt][nt][j] = 0.0f;

    // ---- issue cp.async copies for chunk s into stage s%NSTG ----
    auto issue = [&](int s) {
        uint32_t stg = sb + (uint32_t)((s % NSTG) * ST_SZ);
        int g  = s >> 3;
        int cb = (s & 7) * 32;
        size_t aoff = (size_t)apixoff[g] + cb;
        uint32_t sa = stg + (uint32_t)(arow * 80 + apart * 16);
        cpasync16(sa + ST_AHI, g_featHi + aoff);
        cpasync16(sa + ST_ALO, g_featLo + aoff);
        size_t boff = (size_t)brow * KTOT + s * 32 + bhalf * 16;
        uint32_t sbb = stg + (uint32_t)(brow * 80 + bhalf * 32);
        cpasync16(sbb + ST_B,      g_wH + boff);
        cpasync16(sbb + ST_B + 16, g_wH + boff + 8);
    };

    // ---- compute one chunk from a stage: 2 term sets (Ahi*B + Alo*B) ----
    auto mma_chunk = [&](uint32_t stg) {
        uint32_t Ahi = stg + ST_AHI + a_off, Alo = stg + ST_ALO + a_off;
        uint32_t Bp  = stg + ST_B + b_off;
        uint32_t ahr[2][4], alr[2][4], bb[4][4];
#pragma unroll
        for (int ks = 0; ks < 2; ++ks) {
            uint32_t ko = ks * 32;
            ldsm4(ahr[0], Ahi + ko);
            ldsm4(ahr[1], Ahi + ko + 16 * 80);
#pragma unroll
            for (int bt = 0; bt < 4; ++bt) ldsm4(bb[bt], Bp + ko + bt * 16 * 80);
#pragma unroll
            for (int mt = 0; mt < 2; ++mt)
#pragma unroll
                for (int nt = 0; nt < 8; ++nt)
                    mma16816(acc[mt][nt], ahr[mt], bb[nt >> 1][(nt & 1) * 2], bb[nt >> 1][(nt & 1) * 2 + 1]);
            ldsm4(alr[0], Alo + ko);
            ldsm4(alr[1], Alo + ko + 16 * 80);
#pragma unroll
            for (int mt = 0; mt < 2; ++mt)
#pragma unroll
                for (int nt = 0; nt < 8; ++nt)
                    mma16816(acc[mt][nt], alr[mt], bb[nt >> 1][(nt & 1) * 2], bb[nt >> 1][(nt & 1) * 2 + 1]);
        }
    };

    // ---- pipeline: issue-ahead 2, one barrier per chunk (proven structure) ----
    issue(0); cp_commit();
    issue(1); cp_commit();
#pragma unroll 1
    for (int s = 0; s < NCH; ++s) {
        cp_wait1();                 // group s complete (<=1 newest pending)
        __syncthreads();            // stage (s-1)%3 free; stage s visible to all
        if (s + 2 < NCH) issue(s + 2);
        cp_commit();                // unconditional: keeps group count uniform
        mma_chunk(sb + (uint32_t)((s % NSTG) * ST_SZ));
    }
    __syncthreads();

    // ---- epilogue: stage all 128 m-rows x 256 n (131KB), coalesced stores ----
    float* smf = reinterpret_cast<float*>(smem);
    {
        int r0 = wm * 32;
#pragma unroll
        for (int mt = 0; mt < 2; ++mt)
#pragma unroll
            for (int nt = 0; nt < 8; ++nt) {
                int r = r0 + mt * 16 + (lane >> 2);
                int c = wn * 64 + nt * 8 + (lane & 3) * 2;
                smf[r * 257 + c]           = acc[mt][nt][0];
                smf[r * 257 + c + 1]       = acc[mt][nt][1];
                smf[(r + 8) * 257 + c]     = acc[mt][nt][2];
                smf[(r + 8) * 257 + c + 1] = acc[mt][nt][3];
            }
    }
    __syncthreads();
    {
        int w   = tid & 63;
        int hh  = (tid >> 6) & 1;
        int ns0 = tid >> 7;                       // 4 n-streams of 64
        int m   = hh * 64 + w;
        size_t ob = (size_t)b * COUT * HW + (size_t)(h0 + hh) * WW + w;
#pragma unroll
        for (int i = 0; i < 64; ++i) {
            int n = ns0 * 64 + i;
            out[ob + (size_t)n * HW] = smf[m * 257 + n];
        }
    }
}

// ---------------- launch ----------------
extern "C" void kernel_launch(void* const* d_in, const int* in_sizes, int n_in,
                              void* d_out, int out_size) {
    const float* feat  = (const float*)d_in[0];
    const float* wconv = (const float*)d_in[1];
    const int*   scx   = (const int*)d_in[2];
    const int*   scy   = (const int*)d_in[3];
    float* out = (float*)d_out;

    k_split_feat<<<dim3(HW / 32, CIN / 32, BATCH), dim3(32, 8)>>>(feat);
    k_wconv<<<(COUT * KTOT / 4 + 255) / 256, 256>>>(wconv);

    cudaFuncSetAttribute(k_gemm, cudaFuncAttributeMaxDynamicSharedMemorySize, SMEM_BYTES);
    k_gemm<<<BATCH * 32, 512, SMEM_BYTES>>>(scx, scy, out);
}

// round 16
// speedup vs baseline: 2.2112x; 1.4659x over previous
#include <cuda_runtime.h>
#include <cuda_fp16.h>
#include <cstdint>
#include <cstddef>

#define DINL __device__ __forceinline__

// Problem dims
constexpr int BATCH = 8;
constexpr int CIN   = 256;
constexpr int COUT  = 256;
constexpr int HH = 64, WW = 64;
constexpr int HW = HH * WW;          // 4096
constexpr int KTOT = 9 * CIN;        // 2304
constexpr int KC   = 32;             // channels per K-chunk
constexpr int NCH  = KTOT / KC;      // 72 chunks
constexpr int NSTG = 3;              // pipeline stages

// Stage tile layout (fp16, 80B row stride -> conflict-free ldmatrix)
// A: single plane 128 rows x 80B; B: single plane 256 rows x 80B
constexpr int ST_A  = 0;             // 10240
constexpr int ST_B  = 10240;         // 20480
constexpr int ST_SZ = 30720;
constexpr int SMEM_BYTES = 131584;   // max(3*ST_SZ=92160, epilogue 128*257*4=131584)

// Scratch (device globals; no runtime allocation allowed)
__device__ __align__(16) __half g_featH[BATCH * HW * CIN];  // [b][pix][c] fp16
__device__ __align__(16) __half g_wH[COUT * KTOT];          // [o][k]      fp16

// ---------------- prep kernels ----------------
// weights: float4-vectorized fp16 round
__global__ void k_wconv(const float* __restrict__ w) {
    int i = blockIdx.x * blockDim.x + threadIdx.x;
    if (i < COUT * KTOT / 4) {
        float4 v = reinterpret_cast<const float4*>(w)[i];
        __half2 a = __half2(__float2half(v.x), __float2half(v.y));
        __half2 b = __half2(__float2half(v.z), __float2half(v.w));
        reinterpret_cast<__half2*>(g_wH)[i * 2]     = a;
        reinterpret_cast<__half2*>(g_wH)[i * 2 + 1] = b;
    }
}

// feat (B,C,H,W) fp32 -> fp16 channels-last via 32x32 smem transpose
__global__ void k_split_feat(const float* __restrict__ feat) {
    __shared__ float tile[32][33];
    int b  = blockIdx.z;
    int c0 = blockIdx.y * 32;
    int p0 = blockIdx.x * 32;
    int tx = threadIdx.x, ty = threadIdx.y;   // (32, 8)
    const float* src = feat + (size_t)b * CIN * HW;
#pragma unroll
    for (int i = 0; i < 32; i += 8)
        tile[ty + i][tx] = src[(size_t)(c0 + ty + i) * HW + p0 + tx];
    __syncthreads();
#pragma unroll
    for (int i = 0; i < 32; i += 8) {
        size_t o = ((size_t)b * HW + p0 + ty + i) * CIN + c0 + tx;
        g_featH[o] = __float2half(tile[tx][ty + i]);
    }
}

// ---------------- asm helpers ----------------
DINL uint32_t smem_u32(const void* p) {
    uint32_t a;
    asm("{ .reg .u64 t; cvta.to.shared.u64 t, %1; cvt.u32.u64 %0, t; }" : "=r"(a) : "l"(p));
    return a;
}
DINL void cpasync16(uint32_t dst, const void* src) {
    asm volatile("cp.async.cg.shared.global [%0], [%1], 16;" :: "r"(dst), "l"(src));
}
DINL void cp_commit() { asm volatile("cp.async.commit_group;" ::: "memory"); }
DINL void cp_wait1()  { asm volatile("cp.async.wait_group 1;" ::: "memory"); }
DINL void ldsm4(uint32_t r[4], uint32_t addr) {
    asm volatile("ldmatrix.sync.aligned.m8n8.x4.shared.b16 {%0,%1,%2,%3}, [%4];"
                 : "=r"(r[0]), "=r"(r[1]), "=r"(r[2]), "=r"(r[3]) : "r"(addr));
}
DINL void mma16816(float c[4], const uint32_t a[4], uint32_t b0, uint32_t b1) {
    asm volatile("mma.sync.aligned.m16n8k16.row.col.f32.f16.f16.f32 "
                 "{%0,%1,%2,%3}, {%4,%5,%6,%7}, {%8,%9}, {%0,%1,%2,%3};"
                 : "+f"(c[0]), "+f"(c[1]), "+f"(c[2]), "+f"(c[3])
                 : "r"(a[0]), "r"(a[1]), "r"(a[2]), "r"(a[3]), "r"(b0), "r"(b1));
}

// ---------------- fused gather-GEMM ----------------
// Grid: 256 CTAs = 8 batches x 32 h-pairs. CTA tile M=128, N=256, occupancy 1
// (proven best). 512 threads = 16 warps in 4x4; warp tile 32x64.
// Single-term fp16 GEMM: D = fp16(A) * fp16(B), fp32 accumulate.
// Calibrated error model (R15 measured 2.08e-4 for the B-rounding term alone):
// adding the independent A-rounding term -> ~2.9e-4 << 1e-3.
__global__ void __launch_bounds__(512, 1)
k_gemm(const int* __restrict__ scx, const int* __restrict__ scy, float* __restrict__ out) {
    extern __shared__ __align__(128) char smem[];
    uint32_t sb = smem_u32(smem);
    int tid  = threadIdx.x;
    int lane = tid & 31, wid = tid >> 5;
    int wm = wid >> 2, wn = wid & 3;             // 4x4 warp grid
    int b  = blockIdx.x >> 5;
    int h0 = (blockIdx.x & 31) * 2;

    // copy mapping: A 128 rows x 4 x 16B; B 256 rows x 2 x 32B
    int arow  = tid >> 2, apart = tid & 3;
    int ah = h0 + (arow >> 6), aw = arow & 63;
    int apix0 = ah * WW + aw;
    int brow  = tid >> 1, bhalf = tid & 1;

    // Precompute the 9 gather-row element offsets (loop-invariant)
    uint32_t apixoff[9];
    {
        int asamp = apix0 * 8;
        apixoff[0] = (uint32_t)((b * HW + apix0) * CIN + apart * 8);
#pragma unroll
        for (int g = 1; g <= 8; ++g) {
            int si = asamp + g - 1;
            int pix = (__ldg(scy + si) - 1) * WW + (__ldg(scx + si) - 1);
            apixoff[g] = (uint32_t)((b * HW + pix) * CIN + apart * 8);
        }
    }

    // ldmatrix per-lane offsets (within a stage)
    uint32_t a_off = (uint32_t)((wm * 32 + (lane & 15)) * 80 + (lane >> 4) * 16);
    uint32_t b_off = (uint32_t)((wn * 64 + (lane & 7) + (lane >> 4) * 8) * 80
                                + ((lane >> 3) & 1) * 16);

    float acc[2][8][4];
#pragma unroll
    for (int mt = 0; mt < 2; ++mt)
#pragma unroll
        for (int nt = 0; nt < 8; ++nt)
#pragma unroll
            for (int j = 0; j < 4; ++j) acc[mt][nt][j] = 0.0f;

    // ---- issue cp.async copies for chunk s into stage s%NSTG ----
    auto issue = [&](int s) {
        uint32_t stg = sb + (uint32_t)((s % NSTG) * ST_SZ);
        int g  = s >> 3;
        int cb = (s & 7) * 32;
        size_t aoff = (size_t)apixoff[g] + cb;
        uint32_t sa = stg + (uint32_t)(arow * 80 + apart * 16);
        cpasync16(sa + ST_A, g_featH + aoff);
        size_t boff = (size_t)brow * KTOT + s * 32 + bhalf * 16;
        uint32_t sbb = stg + (uint32_t)(brow * 80 + bhalf * 32);
        cpasync16(sbb + ST_B,      g_wH + boff);
        cpasync16(sbb + ST_B + 16, g_wH + boff + 8);
    };

    // ---- compute one chunk from a stage: single term A*B ----
    auto mma_chunk = [&](uint32_t stg) {
        uint32_t Ap = stg + ST_A + a_off;
        uint32_t Bp = stg + ST_B + b_off;
        uint32_t ar[2][4], bb[4][4];
#pragma unroll
        for (int ks = 0; ks < 2; ++ks) {
            uint32_t ko = ks * 32;
            ldsm4(ar[0], Ap + ko);
            ldsm4(ar[1], Ap + ko + 16 * 80);
#pragma unroll
            for (int bt = 0; bt < 4; ++bt) ldsm4(bb[bt], Bp + ko + bt * 16 * 80);
#pragma unroll
            for (int mt = 0; mt < 2; ++mt)
#pragma unroll
                for (int nt = 0; nt < 8; ++nt)
                    mma16816(acc[mt][nt], ar[mt], bb[nt >> 1][(nt & 1) * 2], bb[nt >> 1][(nt & 1) * 2 + 1]);
        }
    };

    // ---- pipeline: issue-ahead 2, one barrier per chunk (proven structure) ----
    issue(0); cp_commit();
    issue(1); cp_commit();
#pragma unroll 1
    for (int s = 0; s < NCH; ++s) {
        cp_wait1();                 // group s complete (<=1 newest pending)
        __syncthreads();            // stage (s-1)%3 free; stage s visible to all
        if (s + 2 < NCH) issue(s + 2);
        cp_commit();                // unconditional: keeps group count uniform
        mma_chunk(sb + (uint32_t)((s % NSTG) * ST_SZ));
    }
    __syncthreads();

    // ---- epilogue: stage all 128 m-rows x 256 n (131KB), coalesced stores ----
    float* smf = reinterpret_cast<float*>(smem);
    {
        int r0 = wm * 32;
#pragma unroll
        for (int mt = 0; mt < 2; ++mt)
#pragma unroll
            for (int nt = 0; nt < 8; ++nt) {
                int r = r0 + mt * 16 + (lane >> 2);
                int c = wn * 64 + nt * 8 + (lane & 3) * 2;
                smf[r * 257 + c]           = acc[mt][nt][0];
                smf[r * 257 + c + 1]       = acc[mt][nt][1];
                smf[(r + 8) * 257 + c]     = acc[mt][nt][2];
                smf[(r + 8) * 257 + c + 1] = acc[mt][nt][3];
            }
    }
    __syncthreads();
    {
        int w   = tid & 63;
        int hh  = (tid >> 6) & 1;
        int ns0 = tid >> 7;                       // 4 n-streams of 64
        int m   = hh * 64 + w;
        size_t ob = (size_t)b * COUT * HW + (size_t)(h0 + hh) * WW + w;
#pragma unroll
        for (int i = 0; i < 64; ++i) {
            int n = ns0 * 64 + i;
            out[ob + (size_t)n * HW] = smf[m * 257 + n];
        }
    }
}

// ---------------- launch ----------------
extern "C" void kernel_launch(void* const* d_in, const int* in_sizes, int n_in,
                              void* d_out, int out_size) {
    const float* feat  = (const float*)d_in[0];
    const float* wconv = (const float*)d_in[1];
    const int*   scx   = (const int*)d_in[2];
    const int*   scy   = (const int*)d_in[3];
    float* out = (float*)d_out;

    k_split_feat<<<dim3(HW / 32, CIN / 32, BATCH), dim3(32, 8)>>>(feat);
    k_wconv<<<(COUT * KTOT / 4 + 255) / 256, 256>>>(wconv);

    cudaFuncSetAttribute(k_gemm, cudaFuncAttributeMaxDynamicSharedMemorySize, SMEM_BYTES);
    k_gemm<<<BATCH * 32, 512, SMEM_BYTES>>>(scx, scy, out);
}